// round 13
// baseline (speedup 1.0000x reference)
#include <cuda_runtime.h>
#include <cuda_fp16.h>
#include <math.h>
#include <stdint.h>

#define HD 2048
#define ID 2048
#define NE 7
#define NMAX 4096

#define TM 128
#define TN 128
#define TK 32                 // fp16 k per stage

// smem layout (bytes, per stage)
#define A_STRIDE 80           // 32 fp16 (64B) + 16 pad
#define B_STRIDE 272          // 128 fp16 (256B) + 16 pad
#define OFF_AL 10240          // A hi tile = 128*80
#define OFF_B  20480
#define STAGE  29184          // 20480 + 32*272
#define NSTAGE 3
#define SMEM_GEMM (NSTAGE * STAGE + 640)

#define NPERS 296             // persistent CTAs (2 per SM x 148)

// ---------------- device scratch ----------------
__device__ __align__(16) float g_eo[(size_t)NMAX * 3 * HD];
__device__ int   g_cnt[8];
__device__ int   g_list[NE * NMAX];
__device__ float g_w[NMAX * 2];
__device__ int   g_tctr[4];            // per-phase persistent tile counters
__device__ int   g_mbc[8];             // m-blocks per expert
__device__ int   g_pref[9];            // tile prefix sums
__device__ int   g_ttotal;
// fp16 weights (single rounding), [mat*8+e][k][n]
__device__ __align__(16) __half g_Wf[(size_t)24 * 2048 * 2048];
// fp16 hi/lo activations
__device__ __align__(16) __half g_xh[(size_t)NMAX * HD];
__device__ __align__(16) __half g_xl[(size_t)NMAX * HD];
__device__ __align__(16) __half g_uh[(size_t)NMAX * 3 * ID];
__device__ __align__(16) __half g_ul[(size_t)NMAX * 3 * ID];
__device__ __align__(16) __half g_gh[(size_t)NMAX * 3 * ID];
__device__ __align__(16) __half g_gl[(size_t)NMAX * 3 * ID];
__device__ __align__(16) __half g_zero[2048];   // zero-initialized, never written

// ---------------- helpers ----------------
__device__ __forceinline__ uint32_t s2u(const void* p) {
    uint32_t a;
    asm("{ .reg .u64 t; cvta.to.shared.u64 t, %1; cvt.u32.u64 %0, t; }" : "=r"(a) : "l"(p));
    return a;
}
#define CP16(dst, src) \
    asm volatile("cp.async.cg.shared.global [%0], [%1], 16;" :: "r"(dst), "l"(src))
#define CP_COMMIT() asm volatile("cp.async.commit_group;" ::: "memory")
#define CP_WAIT(n)  asm volatile("cp.async.wait_group %0;" :: "n"(n) : "memory")

__device__ __forceinline__ void mma_f16(float* c, const unsigned* a, const unsigned* b) {
    asm volatile(
        "mma.sync.aligned.m16n8k16.row.col.f32.f16.f16.f32 "
        "{%0,%1,%2,%3}, {%4,%5,%6,%7}, {%8,%9}, {%0,%1,%2,%3};"
        : "+f"(c[0]), "+f"(c[1]), "+f"(c[2]), "+f"(c[3])
        : "r"(a[0]), "r"(a[1]), "r"(a[2]), "r"(a[3]), "r"(b[0]), "r"(b[1]));
}
__device__ __forceinline__ void split2h(float x, float y, __half2* hp, __half2* lp) {
    __half hx = __float2half(x), hy = __float2half(y);
    hp->x = hx; hp->y = hy;
    lp->x = __float2half(x - __half2float(hx));
    lp->y = __float2half(y - __half2float(hy));
}

// ---------------- reset (graph-replay safe) ----------------
__global__ void zero_cnt_kernel() {
    if (threadIdx.x < 8) g_cnt[threadIdx.x] = 0;
    if (threadIdx.x < 4) g_tctr[threadIdx.x] = 0;
}

// ---------------- router ----------------
__global__ void router_kernel(const float* __restrict__ x,
                              const float* __restrict__ Wr,
                              const float* __restrict__ br,
                              const float* __restrict__ gbias,
                              int Ntok) {
    int t = blockIdx.x * blockDim.y + threadIdx.y;
    if (t >= Ntok) return;
    int lane = threadIdx.x;

    float acc[NE];
#pragma unroll
    for (int e = 0; e < NE; e++) acc[e] = 0.f;

    const float* xr = x + (size_t)t * HD;
    for (int h = lane; h < HD; h += 32) {
        float xv = xr[h];
#pragma unroll
        for (int e = 0; e < NE; e++)
            acc[e] = fmaf(xv, Wr[h * NE + e], acc[e]);
    }
#pragma unroll
    for (int off = 16; off > 0; off >>= 1) {
#pragma unroll
        for (int e = 0; e < NE; e++)
            acc[e] += __shfl_down_sync(0xffffffffu, acc[e], off);
    }

    if (lane == 0) {
        float logit[NE], bl[NE];
#pragma unroll
        for (int e = 0; e < NE; e++) {
            logit[e] = acc[e] + br[e];
            bl[e]    = logit[e] + gbias[e];
        }
        int i0 = 0;
#pragma unroll
        for (int e = 1; e < NE; e++) if (bl[e] > bl[i0]) i0 = e;
        int i1 = -1;
#pragma unroll
        for (int e = 0; e < NE; e++) {
            if (e == i0) continue;
            if (i1 < 0 || bl[e] > bl[i1]) i1 = e;
        }
        float l0 = logit[i0], l1 = logit[i1];
        float m  = fmaxf(l0, l1);
        float e0 = expf(l0 - m), e1 = expf(l1 - m);
        float inv = 1.f / (e0 + e1);
        g_w[t * 2 + 0] = e0 * inv;
        g_w[t * 2 + 1] = e1 * inv;

        int p0 = atomicAdd(&g_cnt[i0], 1);
        g_list[i0 * NMAX + p0] = t * 3 + 0;
        int p1 = atomicAdd(&g_cnt[i1], 1);
        g_list[i1 * NMAX + p1] = t * 3 + 1;
    }
}

// ---------------- tile plan ----------------
__global__ void plan_kernel(int Ntok) {
    if (threadIdx.x == 0) {
        int p = 0;
        for (int e = 0; e < 8; e++) {
            int c  = (e < NE) ? g_cnt[e] : Ntok;
            int mb = (c + TM - 1) / TM;
            g_mbc[e]  = mb;
            g_pref[e] = p;
            p += mb * (2048 / TN);
        }
        g_pref[8] = p;
        g_ttotal  = p;
    }
}

// ---------------- weight fp16 convert ----------------
__global__ void split_w_kernel(const float* __restrict__ Wup,
                               const float* __restrict__ Wg,
                               const float* __restrict__ Wd,
                               const float* __restrict__ Wsu,
                               const float* __restrict__ Wsg,
                               const float* __restrict__ Wsd) {
    int me  = blockIdx.y;                  // 0..23
    int mat = me >> 3, e = me & 7;
    const float* src;
    if (mat == 0)      src = (e < NE) ? Wup + (size_t)e * 4194304 : Wsu;
    else if (mat == 1) src = (e < NE) ? Wg  + (size_t)e * 4194304 : Wsg;
    else               src = (e < NE) ? Wd  + (size_t)e * 4194304 : Wsd;

    size_t i4 = (size_t)blockIdx.x * blockDim.x + threadIdx.x;   // float4 index
    float4 v = ((const float4*)src)[i4];
    __half2 h0, h1;
    h0.x = __float2half(v.x); h0.y = __float2half(v.y);
    h1.x = __float2half(v.z); h1.y = __float2half(v.w);
    uint2 uh; uh.x = *(uint32_t*)&h0; uh.y = *(uint32_t*)&h1;
    *(uint2*)(g_Wf + ((size_t)me << 22) + i4 * 4) = uh;
}

// ---------------- activation fp16 hi/lo split ----------------
__global__ void split_x_kernel(const float* __restrict__ x, int n4) {
    int i4 = blockIdx.x * blockDim.x + threadIdx.x;
    if (i4 >= n4) return;
    float4 v = ((const float4*)x)[i4];
    __half2 h0, h1, l0, l1;
    split2h(v.x, v.y, &h0, &l0);
    split2h(v.z, v.w, &h1, &l1);
    size_t o = (size_t)i4 * 4;
    uint2 uh; uh.x = *(uint32_t*)&h0; uh.y = *(uint32_t*)&h1;
    uint2 ul; ul.x = *(uint32_t*)&l0; ul.y = *(uint32_t*)&l1;
    *(uint2*)(g_xh + o) = uh;
    *(uint2*)(g_xl + o) = ul;
}

// ---------------- persistent 3-stage cp.async fp16 2-pass gather-GEMM ----------------
template<int PHASE>
__global__ __launch_bounds__(256, 2)
void gemm_kernel(const float* __restrict__ bias,
                 const float* __restrict__ biass,
                 int Ntok) {
    extern __shared__ char smem[];
    const int tid  = threadIdx.x;
    const int lane = tid & 31;
    const int wid  = tid >> 5;
    const int wm   = wid & 3;
    const int wn   = wid >> 2;

    const uint32_t sb = s2u(smem);
    int* slots  = (int*)(smem + NSTAGE * STAGE);
    int* s_tile = (int*)(smem + NSTAGE * STAGE + 520);

    const int NK = 2048 / TK;   // 64

    for (;;) {
        // -------- fetch next tile --------
        __syncthreads();                       // protect slots/smem from prev tile
        if (tid == 0) *s_tile = atomicAdd(&g_tctr[PHASE], 1);
        __syncthreads();
        const int t = *s_tile;
        if (t >= g_ttotal) break;

        int e = 0;
        while (t >= g_pref[e + 1]) e++;
        const int local = t - g_pref[e];
        const int nb    = local & (2048 / TN - 1);
        const int mb    = local / (2048 / TN);
        const int cnt   = (e < NE) ? g_cnt[e] : Ntok;
        const int m0    = mb * TM;
        const int n0    = nb * TN;
        const float* __restrict__ bv = (e < NE) ? bias + (size_t)e * 2048 : biass;

        if (tid < TM) {
            int m = m0 + tid;
            slots[tid] = (m < cnt) ? ((e < NE) ? g_list[e * NMAX + m] : m * 3 + 2) : -1;
        }
        __syncthreads();

        // ---- cp.async assignments ----
        const int arow = tid >> 1;
        const int au   = (tid & 1) * 2;
        const __half *a_h, *a_l;
        {
            int slot = slots[arow];
            if (slot >= 0) {
                if (PHASE == 0)      { a_h = g_xh + (size_t)(slot / 3) * HD; a_l = g_xl + (size_t)(slot / 3) * HD; }
                else if (PHASE == 1) { a_h = g_uh + (size_t)slot * ID;       a_l = g_ul + (size_t)slot * ID; }
                else                 { a_h = g_gh + (size_t)slot * ID;       a_l = g_gl + (size_t)slot * ID; }
                a_h += au * 8; a_l += au * 8;
            } else { a_h = g_zero + au * 8; a_l = g_zero + au * 8; }
        }
        const uint32_t a_dst = sb + arow * A_STRIDE + au * 16;
        const bool a_valid = (slots[arow] >= 0);

        const int brow = tid >> 3;
        const int bu   = (tid & 7) * 2;
        const __half* wbase = g_Wf + ((size_t)(PHASE * 8 + e) << 22) + (size_t)brow * 2048 + n0 + bu * 8;
        const uint32_t b_dst = sb + OFF_B + brow * B_STRIDE + bu * 16;

        // ---- ldmatrix base addresses ----
        uint32_t a_addr[2], b_addr;
        {
            int row  = wm * 32 + (lane & 15);
            int colB = (lane >> 4) * 16;
#pragma unroll
            for (int mt = 0; mt < 2; mt++)
                a_addr[mt] = sb + (row + mt * 16) * A_STRIDE + colB;
            b_addr = sb + OFF_B + (lane & 15) * B_STRIDE + wn * 128 + (lane >> 4) * 16;
        }

        float acc[2][8][4];
#pragma unroll
        for (int mt = 0; mt < 2; mt++)
#pragma unroll
            for (int nt = 0; nt < 8; nt++)
#pragma unroll
                for (int j = 0; j < 4; j++) acc[mt][nt][j] = 0.f;

        auto issue_loads = [&](int kn) {
            const uint32_t so = (uint32_t)(kn % NSTAGE) * STAGE;
            const int k0 = kn * TK;
            const int ka = a_valid ? k0 : 0;
            uint32_t d  = a_dst + so;
            uint32_t db = b_dst + so;
            const __half* bh = wbase + (size_t)k0 * 2048;
            CP16(d,            a_h + ka);   CP16(d + 16,            a_h + ka + 8);
            CP16(d + OFF_AL,   a_l + ka);   CP16(d + OFF_AL + 16,   a_l + ka + 8);
            CP16(db,           bh);         CP16(db + 16,           bh + 8);
        };

        // ---- prologue ----
        issue_loads(0); CP_COMMIT();
        issue_loads(1); CP_COMMIT();

        for (int kt = 0; kt < NK; kt++) {
            CP_WAIT(1);
            __syncthreads();

            if (kt + 2 < NK) issue_loads(kt + 2);
            CP_COMMIT();

            const uint32_t so = (uint32_t)(kt % NSTAGE) * STAGE;
#pragma unroll
            for (int ks = 0; ks < 2; ks++) {
                unsigned ah[2][4], al[2][4];
#pragma unroll
                for (int mt = 0; mt < 2; mt++) {
                    uint32_t ad = a_addr[mt] + so + ks * 32;
                    asm volatile("ldmatrix.sync.aligned.m8n8.x4.shared.b16 {%0,%1,%2,%3}, [%4];"
                        : "=r"(ah[mt][0]), "=r"(ah[mt][1]), "=r"(ah[mt][2]), "=r"(ah[mt][3])
                        : "r"(ad));
                    asm volatile("ldmatrix.sync.aligned.m8n8.x4.shared.b16 {%0,%1,%2,%3}, [%4];"
                        : "=r"(al[mt][0]), "=r"(al[mt][1]), "=r"(al[mt][2]), "=r"(al[mt][3])
                        : "r"(ad + OFF_AL));
                }
#pragma unroll
                for (int np = 0; np < 4; np++) {
                    uint32_t bd = b_addr + so + ks * (16 * B_STRIDE) + np * 32;
                    unsigned bq[4];
                    asm volatile("ldmatrix.sync.aligned.m8n8.x4.trans.shared.b16 {%0,%1,%2,%3}, [%4];"
                        : "=r"(bq[0]), "=r"(bq[1]), "=r"(bq[2]), "=r"(bq[3]) : "r"(bd));
#pragma unroll
                    for (int mt = 0; mt < 2; mt++) {
                        mma_f16(acc[mt][np * 2 + 0], ah[mt], bq + 0);
                        mma_f16(acc[mt][np * 2 + 0], al[mt], bq + 0);
                        mma_f16(acc[mt][np * 2 + 1], ah[mt], bq + 2);
                        mma_f16(acc[mt][np * 2 + 1], al[mt], bq + 2);
                    }
                }
            }
        }

        // ---- epilogue ----
        const int tg = lane >> 2, t4 = lane & 3;
#pragma unroll
        for (int mt = 0; mt < 2; mt++) {
#pragma unroll
            for (int nt = 0; nt < 8; nt++) {
                int col = n0 + wn * 64 + nt * 8 + t4 * 2;
                float2 bb = *(const float2*)(bv + col);
#pragma unroll
                for (int half = 0; half < 2; half++) {
                    int rl = wm * 32 + mt * 16 + tg + half * 8;
                    if (m0 + rl >= cnt) continue;
                    int slot = slots[rl];
                    float zx = acc[mt][nt][half * 2 + 0] + bb.x;
                    float zy = acc[mt][nt][half * 2 + 1] + bb.y;
                    if (PHASE == 0) {
                        __half2 hp, lp;
                        split2h(zx, zy, &hp, &lp);
                        *(__half2*)(g_uh + (size_t)slot * ID + col) = hp;
                        *(__half2*)(g_ul + (size_t)slot * ID + col) = lp;
                    } else if (PHASE == 1) {
                        __half2 uh2 = *(const __half2*)(g_uh + (size_t)slot * ID + col);
                        __half2 ul2 = *(const __half2*)(g_ul + (size_t)slot * ID + col);
                        float ux = __half2float(uh2.x) + __half2float(ul2.x);
                        float uy = __half2float(uh2.y) + __half2float(ul2.y);
                        float ox = (zx / (1.f + expf(-zx))) * ux;
                        float oy = (zy / (1.f + expf(-zy))) * uy;
                        __half2 hp, lp;
                        split2h(ox, oy, &hp, &lp);
                        *(__half2*)(g_gh + (size_t)slot * ID + col) = hp;
                        *(__half2*)(g_gl + (size_t)slot * ID + col) = lp;
                    } else {
                        *(float2*)(g_eo + (size_t)slot * HD + col) = make_float2(zx, zy);
                    }
                }
            }
        }
    }
}

// ---------------- combine ----------------
__global__ void combine_kernel(float* __restrict__ out, int Ntok) {
    int i = blockIdx.x * blockDim.x + threadIdx.x;
    int total = Ntok * (HD / 4);
    if (i >= total) return;
    int t  = i / (HD / 4);
    int h4 = i - t * (HD / 4);
    float w0 = g_w[t * 2 + 0];
    float w1 = g_w[t * 2 + 1];
    const float4* e0 = (const float4*)&g_eo[(size_t)(t * 3 + 0) * HD];
    const float4* e1 = (const float4*)&g_eo[(size_t)(t * 3 + 1) * HD];
    const float4* e2 = (const float4*)&g_eo[(size_t)(t * 3 + 2) * HD];
    float4 a = e0[h4], b = e1[h4], c = e2[h4];
    float4 o;
    o.x = fmaf(w0, a.x, fmaf(w1, b.x, c.x));
    o.y = fmaf(w0, a.y, fmaf(w1, b.y, c.y));
    o.z = fmaf(w0, a.z, fmaf(w1, b.z, c.z));
    o.w = fmaf(w0, a.w, fmaf(w1, b.w, c.w));
    ((float4*)out)[i] = o;
}

// ---------------- launch ----------------
extern "C" void kernel_launch(void* const* d_in, const int* in_sizes, int n_in,
                              void* d_out, int out_size) {
    const float* x    = (const float*)d_in[0];
    const float* Wr   = (const float*)d_in[1];
    const float* br   = (const float*)d_in[2];
    const float* gb   = (const float*)d_in[3];
    const float* Wup  = (const float*)d_in[4];
    const float* bup  = (const float*)d_in[5];
    const float* Wg   = (const float*)d_in[6];
    const float* bg   = (const float*)d_in[7];
    const float* Wd   = (const float*)d_in[8];
    const float* bd   = (const float*)d_in[9];
    const float* Wsu  = (const float*)d_in[10];
    const float* bsu  = (const float*)d_in[11];
    const float* Wsg  = (const float*)d_in[12];
    const float* bsg  = (const float*)d_in[13];
    const float* Wsd  = (const float*)d_in[14];
    const float* bsd  = (const float*)d_in[15];

    int Ntok = in_sizes[0] / HD;
    if (Ntok > NMAX) Ntok = NMAX;

    cudaFuncSetAttribute(gemm_kernel<0>, cudaFuncAttributeMaxDynamicSharedMemorySize, SMEM_GEMM);
    cudaFuncSetAttribute(gemm_kernel<1>, cudaFuncAttributeMaxDynamicSharedMemorySize, SMEM_GEMM);
    cudaFuncSetAttribute(gemm_kernel<2>, cudaFuncAttributeMaxDynamicSharedMemorySize, SMEM_GEMM);

    zero_cnt_kernel<<<1, 32>>>();
    router_kernel<<<(Ntok + 3) / 4, dim3(32, 4)>>>(x, Wr, br, gb, Ntok);
    plan_kernel<<<1, 32>>>(Ntok);
    split_x_kernel<<<(Ntok * (HD / 4) + 255) / 256, 256>>>(x, Ntok * (HD / 4));
    split_w_kernel<<<dim3(4096, 24), 256>>>(Wup, Wg, Wd, Wsu, Wsg, Wsd);

    gemm_kernel<0><<<NPERS, 256, SMEM_GEMM>>>(bup, bsu, Ntok);
    gemm_kernel<1><<<NPERS, 256, SMEM_GEMM>>>(bg,  bsg, Ntok);
    gemm_kernel<2><<<NPERS, 256, SMEM_GEMM>>>(bd,  bsd, Ntok);

    int total4 = Ntok * (HD / 4);
    combine_kernel<<<(total4 + 255) / 256, 256>>>((float*)d_out, Ntok);
}

// round 15
// speedup vs baseline: 1.7338x; 1.7338x over previous
#include <cuda_runtime.h>
#include <cuda_fp16.h>
#include <math.h>
#include <stdint.h>

#define HD 2048
#define ID 2048
#define NE 7
#define NMAX 4096

#define TM 128
#define TN 128
#define TK 32                 // fp16 k per stage

// smem layout (bytes, per stage)
#define A_STRIDE 80           // 32 fp16 (64B) + 16 pad
#define B_STRIDE 272          // 128 fp16 (256B) + 16 pad
#define OFF_B  10240          // A tile = 128*80
#define STAGE  18944          // 10240 + 32*272
#define NSTAGE 3
#define SMEM_GEMM (NSTAGE * STAGE + 640)

// ---------------- device scratch ----------------
__device__ __align__(16) float g_eo[(size_t)NMAX * 3 * HD];
__device__ int   g_cnt[8];
__device__ int   g_list[NE * NMAX];
__device__ float g_w[NMAX * 2];
// fp16 weights (single rounding), [mat*8+e][k][n]
__device__ __align__(16) __half g_Wf[(size_t)24 * 2048 * 2048];
// fp16 activations: x single; u hi/lo (SwiGLU multiplier precision); g single
__device__ __align__(16) __half g_xf[(size_t)NMAX * HD];
__device__ __align__(16) __half g_uh[(size_t)NMAX * 3 * ID];
__device__ __align__(16) __half g_ul[(size_t)NMAX * 3 * ID];
__device__ __align__(16) __half g_gf[(size_t)NMAX * 3 * ID];
__device__ __align__(16) __half g_zero[2048];   // zero-initialized, never written

// ---------------- helpers ----------------
__device__ __forceinline__ uint32_t s2u(const void* p) {
    uint32_t a;
    asm("{ .reg .u64 t; cvta.to.shared.u64 t, %1; cvt.u32.u64 %0, t; }" : "=r"(a) : "l"(p));
    return a;
}
#define CP16(dst, src) \
    asm volatile("cp.async.cg.shared.global [%0], [%1], 16;" :: "r"(dst), "l"(src))
#define CP_COMMIT() asm volatile("cp.async.commit_group;" ::: "memory")
#define CP_WAIT(n)  asm volatile("cp.async.wait_group %0;" :: "n"(n) : "memory")

__device__ __forceinline__ void mma_f16(float* c, const unsigned* a, const unsigned* b) {
    asm volatile(
        "mma.sync.aligned.m16n8k16.row.col.f32.f16.f16.f32 "
        "{%0,%1,%2,%3}, {%4,%5,%6,%7}, {%8,%9}, {%0,%1,%2,%3};"
        : "+f"(c[0]), "+f"(c[1]), "+f"(c[2]), "+f"(c[3])
        : "r"(a[0]), "r"(a[1]), "r"(a[2]), "r"(a[3]), "r"(b[0]), "r"(b[1]));
}
__device__ __forceinline__ void split2h(float x, float y, __half2* hp, __half2* lp) {
    __half hx = __float2half(x), hy = __float2half(y);
    hp->x = hx; hp->y = hy;
    lp->x = __float2half(x - __half2float(hx));
    lp->y = __float2half(y - __half2float(hy));
}

// ---------------- reset (graph-replay safe) ----------------
__global__ void zero_cnt_kernel() {
    if (threadIdx.x < 8) g_cnt[threadIdx.x] = 0;
}

// ---------------- router ----------------
__global__ void router_kernel(const float* __restrict__ x,
                              const float* __restrict__ Wr,
                              const float* __restrict__ br,
                              const float* __restrict__ gbias,
                              int Ntok) {
    int t = blockIdx.x * blockDim.y + threadIdx.y;
    if (t >= Ntok) return;
    int lane = threadIdx.x;

    float acc[NE];
#pragma unroll
    for (int e = 0; e < NE; e++) acc[e] = 0.f;

    const float* xr = x + (size_t)t * HD;
    for (int h = lane; h < HD; h += 32) {
        float xv = xr[h];
#pragma unroll
        for (int e = 0; e < NE; e++)
            acc[e] = fmaf(xv, Wr[h * NE + e], acc[e]);
    }
#pragma unroll
    for (int off = 16; off > 0; off >>= 1) {
#pragma unroll
        for (int e = 0; e < NE; e++)
            acc[e] += __shfl_down_sync(0xffffffffu, acc[e], off);
    }

    if (lane == 0) {
        float logit[NE], bl[NE];
#pragma unroll
        for (int e = 0; e < NE; e++) {
            logit[e] = acc[e] + br[e];
            bl[e]    = logit[e] + gbias[e];
        }
        int i0 = 0;
#pragma unroll
        for (int e = 1; e < NE; e++) if (bl[e] > bl[i0]) i0 = e;
        int i1 = -1;
#pragma unroll
        for (int e = 0; e < NE; e++) {
            if (e == i0) continue;
            if (i1 < 0 || bl[e] > bl[i1]) i1 = e;
        }
        float l0 = logit[i0], l1 = logit[i1];
        float m  = fmaxf(l0, l1);
        float e0 = expf(l0 - m), e1 = expf(l1 - m);
        float inv = 1.f / (e0 + e1);
        g_w[t * 2 + 0] = e0 * inv;
        g_w[t * 2 + 1] = e1 * inv;

        int p0 = atomicAdd(&g_cnt[i0], 1);
        g_list[i0 * NMAX + p0] = t * 3 + 0;
        int p1 = atomicAdd(&g_cnt[i1], 1);
        g_list[i1 * NMAX + p1] = t * 3 + 1;
    }
}

// ---------------- weight fp16 convert ----------------
__global__ void split_w_kernel(const float* __restrict__ Wup,
                               const float* __restrict__ Wg,
                               const float* __restrict__ Wd,
                               const float* __restrict__ Wsu,
                               const float* __restrict__ Wsg,
                               const float* __restrict__ Wsd) {
    int me  = blockIdx.y;                  // 0..23
    int mat = me >> 3, e = me & 7;
    const float* src;
    if (mat == 0)      src = (e < NE) ? Wup + (size_t)e * 4194304 : Wsu;
    else if (mat == 1) src = (e < NE) ? Wg  + (size_t)e * 4194304 : Wsg;
    else               src = (e < NE) ? Wd  + (size_t)e * 4194304 : Wsd;

    size_t i4 = (size_t)blockIdx.x * blockDim.x + threadIdx.x;   // float4 index
    float4 v = ((const float4*)src)[i4];
    __half2 h0, h1;
    h0.x = __float2half(v.x); h0.y = __float2half(v.y);
    h1.x = __float2half(v.z); h1.y = __float2half(v.w);
    uint2 uh; uh.x = *(uint32_t*)&h0; uh.y = *(uint32_t*)&h1;
    *(uint2*)(g_Wf + ((size_t)me << 22) + i4 * 4) = uh;
}

// ---------------- activation fp16 convert ----------------
__global__ void split_x_kernel(const float* __restrict__ x, int n4) {
    int i4 = blockIdx.x * blockDim.x + threadIdx.x;
    if (i4 >= n4) return;
    float4 v = ((const float4*)x)[i4];
    __half2 h0, h1;
    h0.x = __float2half(v.x); h0.y = __float2half(v.y);
    h1.x = __float2half(v.z); h1.y = __float2half(v.w);
    uint2 uh; uh.x = *(uint32_t*)&h0; uh.y = *(uint32_t*)&h1;
    *(uint2*)(g_xf + (size_t)i4 * 4) = uh;
}

// ---------------- 3-stage cp.async fp16 1-pass gather-GEMM ----------------
template<int PHASE>
__global__ __launch_bounds__(256, 2)
void gemm_kernel(const float* __restrict__ bias,
                 const float* __restrict__ biass,
                 int Ntok) {
    extern __shared__ char smem[];
    const int e   = blockIdx.z;
    const int cnt = (e < NE) ? g_cnt[e] : Ntok;
    const int m0  = blockIdx.y * TM;
    if (m0 >= cnt) return;
    const int n0  = blockIdx.x * TN;
    const float* __restrict__ bv = (e < NE) ? bias + (size_t)e * 2048 : biass;

    const int tid  = threadIdx.x;
    const int lane = tid & 31;
    const int wid  = tid >> 5;
    const int wm   = wid & 3;
    const int wn   = wid >> 2;

    const uint32_t sb = s2u(smem);
    int* slots = (int*)(smem + NSTAGE * STAGE);

    if (tid < TM) {
        int m = m0 + tid;
        slots[tid] = (m < cnt) ? ((e < NE) ? g_list[e * NMAX + m] : m * 3 + 2) : -1;
    }
    __syncthreads();

    // ---- cp.async assignments ----
    const int arow = tid >> 1;
    const int au   = (tid & 1) * 2;          // A 16B units au, au+1
    const __half* a_p;
    {
        int slot = slots[arow];
        if (slot >= 0) {
            if (PHASE == 0)      a_p = g_xf + (size_t)(slot / 3) * HD;
            else if (PHASE == 1) a_p = g_uh + (size_t)slot * ID;
            else                 a_p = g_gf + (size_t)slot * ID;
            a_p += au * 8;
        } else a_p = g_zero + au * 8;
    }
    const uint32_t a_dst = sb + arow * A_STRIDE + au * 16;
    const bool a_valid = (slots[arow] >= 0);

    const int brow = tid >> 3;               // B k-row 0..31
    const int bu   = (tid & 7) * 2;          // B 16B units bu, bu+1
    const __half* wbase = g_Wf + ((size_t)(PHASE * 8 + e) << 22) + (size_t)brow * 2048 + n0 + bu * 8;
    const uint32_t b_dst = sb + OFF_B + brow * B_STRIDE + bu * 16;

    // ---- ldmatrix base addresses ----
    uint32_t a_addr[2], b_addr;
    {
        int row  = wm * 32 + (lane & 15);
        int colB = (lane >> 4) * 16;
#pragma unroll
        for (int mt = 0; mt < 2; mt++)
            a_addr[mt] = sb + (row + mt * 16) * A_STRIDE + colB;
        b_addr = sb + OFF_B + (lane & 15) * B_STRIDE + wn * 128 + (lane >> 4) * 16;
    }

    float acc[2][8][4];
#pragma unroll
    for (int mt = 0; mt < 2; mt++)
#pragma unroll
        for (int nt = 0; nt < 8; nt++)
#pragma unroll
            for (int j = 0; j < 4; j++) acc[mt][nt][j] = 0.f;

    const int NK = 2048 / TK;   // 64

    auto issue_loads = [&](int kn) {
        const uint32_t so = (uint32_t)(kn % NSTAGE) * STAGE;
        const int k0 = kn * TK;
        const int ka = a_valid ? k0 : 0;
        uint32_t d  = a_dst + so;
        uint32_t db = b_dst + so;
        const __half* bh = wbase + (size_t)k0 * 2048;
        CP16(d,  a_p + ka);   CP16(d + 16,  a_p + ka + 8);
        CP16(db, bh);         CP16(db + 16, bh + 8);
    };

    // ---- prologue: fill stages 0,1 ----
    issue_loads(0); CP_COMMIT();
    issue_loads(1); CP_COMMIT();

    for (int kt = 0; kt < NK; kt++) {
        CP_WAIT(1);
        __syncthreads();

        if (kt + 2 < NK) issue_loads(kt + 2);
        CP_COMMIT();

        const uint32_t so = (uint32_t)(kt % NSTAGE) * STAGE;
#pragma unroll
        for (int ks = 0; ks < 2; ks++) {
            unsigned ah[2][4];
#pragma unroll
            for (int mt = 0; mt < 2; mt++) {
                uint32_t ad = a_addr[mt] + so + ks * 32;
                asm volatile("ldmatrix.sync.aligned.m8n8.x4.shared.b16 {%0,%1,%2,%3}, [%4];"
                    : "=r"(ah[mt][0]), "=r"(ah[mt][1]), "=r"(ah[mt][2]), "=r"(ah[mt][3])
                    : "r"(ad));
            }
#pragma unroll
            for (int np = 0; np < 4; np++) {
                uint32_t bd = b_addr + so + ks * (16 * B_STRIDE) + np * 32;
                unsigned bq[4];
                asm volatile("ldmatrix.sync.aligned.m8n8.x4.trans.shared.b16 {%0,%1,%2,%3}, [%4];"
                    : "=r"(bq[0]), "=r"(bq[1]), "=r"(bq[2]), "=r"(bq[3]) : "r"(bd));
#pragma unroll
                for (int mt = 0; mt < 2; mt++) {
                    mma_f16(acc[mt][np * 2 + 0], ah[mt], bq + 0);
                    mma_f16(acc[mt][np * 2 + 1], ah[mt], bq + 2);
                }
            }
        }
    }

    // ---- epilogue ----
    const int tg = lane >> 2, t4 = lane & 3;
#pragma unroll
    for (int mt = 0; mt < 2; mt++) {
#pragma unroll
        for (int nt = 0; nt < 8; nt++) {
            int col = n0 + wn * 64 + nt * 8 + t4 * 2;
            float2 bb = *(const float2*)(bv + col);
#pragma unroll
            for (int half = 0; half < 2; half++) {
                int rl = wm * 32 + mt * 16 + tg + half * 8;
                if (m0 + rl >= cnt) continue;
                int slot = slots[rl];
                float zx = acc[mt][nt][half * 2 + 0] + bb.x;
                float zy = acc[mt][nt][half * 2 + 1] + bb.y;
                if (PHASE == 0) {
                    __half2 hp, lp;
                    split2h(zx, zy, &hp, &lp);
                    *(__half2*)(g_uh + (size_t)slot * ID + col) = hp;
                    *(__half2*)(g_ul + (size_t)slot * ID + col) = lp;
                } else if (PHASE == 1) {
                    __half2 uh2 = *(const __half2*)(g_uh + (size_t)slot * ID + col);
                    __half2 ul2 = *(const __half2*)(g_ul + (size_t)slot * ID + col);
                    float ux = __half2float(uh2.x) + __half2float(ul2.x);
                    float uy = __half2float(uh2.y) + __half2float(ul2.y);
                    float ox = (zx / (1.f + expf(-zx))) * ux;
                    float oy = (zy / (1.f + expf(-zy))) * uy;
                    __half2 gp;
                    gp.x = __float2half(ox); gp.y = __float2half(oy);
                    *(__half2*)(g_gf + (size_t)slot * ID + col) = gp;
                } else {
                    *(float2*)(g_eo + (size_t)slot * HD + col) = make_float2(zx, zy);
                }
            }
        }
    }
}

// ---------------- combine ----------------
__global__ void combine_kernel(float* __restrict__ out, int Ntok) {
    int i = blockIdx.x * blockDim.x + threadIdx.x;
    int total = Ntok * (HD / 4);
    if (i >= total) return;
    int t  = i / (HD / 4);
    int h4 = i - t * (HD / 4);
    float w0 = g_w[t * 2 + 0];
    float w1 = g_w[t * 2 + 1];
    const float4* e0 = (const float4*)&g_eo[(size_t)(t * 3 + 0) * HD];
    const float4* e1 = (const float4*)&g_eo[(size_t)(t * 3 + 1) * HD];
    const float4* e2 = (const float4*)&g_eo[(size_t)(t * 3 + 2) * HD];
    float4 a = e0[h4], b = e1[h4], c = e2[h4];
    float4 o;
    o.x = fmaf(w0, a.x, fmaf(w1, b.x, c.x));
    o.y = fmaf(w0, a.y, fmaf(w1, b.y, c.y));
    o.z = fmaf(w0, a.z, fmaf(w1, b.z, c.z));
    o.w = fmaf(w0, a.w, fmaf(w1, b.w, c.w));
    ((float4*)out)[i] = o;
}

// ---------------- launch ----------------
extern "C" void kernel_launch(void* const* d_in, const int* in_sizes, int n_in,
                              void* d_out, int out_size) {
    const float* x    = (const float*)d_in[0];
    const float* Wr   = (const float*)d_in[1];
    const float* br   = (const float*)d_in[2];
    const float* gb   = (const float*)d_in[3];
    const float* Wup  = (const float*)d_in[4];
    const float* bup  = (const float*)d_in[5];
    const float* Wg   = (const float*)d_in[6];
    const float* bg   = (const float*)d_in[7];
    const float* Wd   = (const float*)d_in[8];
    const float* bd   = (const float*)d_in[9];
    const float* Wsu  = (const float*)d_in[10];
    const float* bsu  = (const float*)d_in[11];
    const float* Wsg  = (const float*)d_in[12];
    const float* bsg  = (const float*)d_in[13];
    const float* Wsd  = (const float*)d_in[14];
    const float* bsd  = (const float*)d_in[15];

    int Ntok = in_sizes[0] / HD;
    if (Ntok > NMAX) Ntok = NMAX;

    cudaFuncSetAttribute(gemm_kernel<0>, cudaFuncAttributeMaxDynamicSharedMemorySize, SMEM_GEMM);
    cudaFuncSetAttribute(gemm_kernel<1>, cudaFuncAttributeMaxDynamicSharedMemorySize, SMEM_GEMM);
    cudaFuncSetAttribute(gemm_kernel<2>, cudaFuncAttributeMaxDynamicSharedMemorySize, SMEM_GEMM);

    zero_cnt_kernel<<<1, 32>>>();
    router_kernel<<<(Ntok + 3) / 4, dim3(32, 4)>>>(x, Wr, br, gb, Ntok);
    split_x_kernel<<<(Ntok * (HD / 4) + 255) / 256, 256>>>(x, Ntok * (HD / 4));
    split_w_kernel<<<dim3(4096, 24), 256>>>(Wup, Wg, Wd, Wsu, Wsg, Wsd);

    dim3 grid(2048 / TN, (Ntok + TM - 1) / TM, 8);
    gemm_kernel<0><<<grid, 256, SMEM_GEMM>>>(bup, bsu, Ntok);
    gemm_kernel<1><<<grid, 256, SMEM_GEMM>>>(bg,  bsg, Ntok);
    gemm_kernel<2><<<grid, 256, SMEM_GEMM>>>(bd,  bsd, Ntok);

    int total4 = Ntok * (HD / 4);
    combine_kernel<<<(total4 + 255) / 256, 256>>>((float*)d_out, Ntok);
}